// round 1
// baseline (speedup 1.0000x reference)
#include <cuda_runtime.h>
#include <cuda_bf16.h>

// Problem constants: outputs [64,512,1000] f32, labels [64,512] i32
#define LBL 1000
#define NROWS_MAX 32768

__device__ int g_argm[NROWS_MAX];
__device__ __align__(16) int g_first[1024];
__device__ __align__(16) int g_idx[1024];

// ---------------------------------------------------------------------------
// K0: reset first-occurrence table (graph replays re-run this each time)
// ---------------------------------------------------------------------------
__global__ void k_init() {
    g_first[threadIdx.x] = 0x7FFFFFFF;
}

// ---------------------------------------------------------------------------
// K1: per-row argmax (original index space) + first-occurrence via atomicMin.
// One warp per row; 250 float4 per row split across 32 lanes.
// ---------------------------------------------------------------------------
__global__ void k_argmax(const float* __restrict__ in,
                         const int* __restrict__ labels, int N) {
    int w    = (blockIdx.x * blockDim.x + threadIdx.x) >> 5;
    int lane = threadIdx.x & 31;
    if (w >= N) return;

    const float4* rp = reinterpret_cast<const float4*>(in) + (size_t)w * 250;
    float bv = -3.402823466e38f;
    int   bi = 0;
#pragma unroll
    for (int it = 0; it < 8; ++it) {
        int k = lane + it * 32;
        if (k < 250) {
            float4 v = rp[k];
            int b = k * 4;
            if (v.x > bv) { bv = v.x; bi = b;     }
            if (v.y > bv) { bv = v.y; bi = b + 1; }
            if (v.z > bv) { bv = v.z; bi = b + 2; }
            if (v.w > bv) { bv = v.w; bi = b + 3; }
        }
    }
#pragma unroll
    for (int off = 16; off > 0; off >>= 1) {
        float ov = __shfl_down_sync(0xFFFFFFFFu, bv, off);
        int   oi = __shfl_down_sync(0xFFFFFFFFu, bi, off);
        if (ov > bv || (ov == bv && oi < bi)) { bv = ov; bi = oi; }
    }
    if (lane == 0) {
        g_argm[w] = bi;
        atomicMin(&g_first[labels[w]], w);
    }
}

// ---------------------------------------------------------------------------
// K2: single block. Rank-sort first-occurrence events by row, run the
// (<=1000-step) serial permutation scan on pinv in smem, invert to g_idx.
//
// Event semantics: r = pinv[m]; if (r != lab) swap(pinv[r], pinv[lab]).
//   (swapping VALUES r,lab in idx_sel <=> swapping pinv entries at r,lab)
// ---------------------------------------------------------------------------
__global__ void k_scan() {
    __shared__ int sf[1024];
    __shared__ int ev_lab[1024];
    __shared__ int ev_m[1024];
    __shared__ int pinv[1024];
    __shared__ int cntE;

    int t = threadIdx.x;
    if (t == 0) cntE = 0;
    sf[t]   = (t < LBL) ? g_first[t] : 0x7FFFFFFF;
    pinv[t] = t;
    __syncthreads();

    int myf = sf[t];
    if (myf != 0x7FFFFFFF) {
        // rank = number of valid events with strictly smaller row index
        // (row indices are distinct, so ranks are a bijection onto [0,E))
        int rank = 0;
#pragma unroll 8
        for (int u = 0; u < 1024; ++u) rank += (sf[u] < myf) ? 1 : 0;
        ev_lab[rank] = t;
        ev_m[rank]   = g_argm[myf];
        atomicAdd(&cntE, 1);
    }
    __syncthreads();

    if (t == 0) {
        int E = cntE;
        for (int e = 0; e < E; ++e) {
            int lab = ev_lab[e];
            int m   = ev_m[e];
            int r   = pinv[m];
            if (r != lab) {
                int pr = pinv[r];
                int pl = pinv[lab];
                pinv[r]   = pl;
                pinv[lab] = pr;
            }
        }
    }
    __syncthreads();

    // forward permutation: idx[pinv[v]] = v  (pinv is a bijection -> full cover)
    if (t < LBL) g_idx[pinv[t]] = t;
}

// ---------------------------------------------------------------------------
// K3: out[n,j] = in[n, idx[j]]. Stage each 4 KB row in smem (coalesced float4
// read), gather from smem, coalesced float4 write. 8 rows per block.
// ---------------------------------------------------------------------------
__global__ void k_gather(const float* __restrict__ in,
                         float* __restrict__ out, int N) {
    __shared__ int4   sidx4[250];
    __shared__ float4 srow4[250];
    const float* srow = reinterpret_cast<const float*>(srow4);

    int t = threadIdx.x;
    if (t < 250) sidx4[t] = reinterpret_cast<const int4*>(g_idx)[t];

    int row0 = blockIdx.x * 8;
#pragma unroll 1
    for (int rr = 0; rr < 8; ++rr) {
        int row = row0 + rr;
        __syncthreads();   // protects srow reuse (and sidx on first iter)
        if (t < 250 && row < N)
            srow4[t] = reinterpret_cast<const float4*>(in + (size_t)row * 1000)[t];
        __syncthreads();
        if (t < 250 && row < N) {
            int4 ii = sidx4[t];
            float4 o;
            o.x = srow[ii.x];
            o.y = srow[ii.y];
            o.z = srow[ii.z];
            o.w = srow[ii.w];
            reinterpret_cast<float4*>(out + (size_t)row * 1000)[t] = o;
        }
    }
}

// ---------------------------------------------------------------------------
extern "C" void kernel_launch(void* const* d_in, const int* in_sizes, int n_in,
                              void* d_out, int out_size) {
    const float* in     = (const float*)d_in[0];
    const int*   labels = (const int*)d_in[1];
    float*       out    = (float*)d_out;
    int N = in_sizes[1];   // 32768 rows; L = 1000

    k_init  <<<1, 1024>>>();
    k_argmax<<<(N + 7) / 8, 256>>>(in, labels, N);
    k_scan  <<<1, 1024>>>();
    k_gather<<<(N + 7) / 8, 256>>>(in, out, N);
}

// round 2
// speedup vs baseline: 1.4647x; 1.4647x over previous
#include <cuda_runtime.h>
#include <cuda_bf16.h>

// Problem constants: outputs [64,512,1000] f32, labels [64,512] i32
#define LBL 1000
#define NROWS_MAX 32768

__device__ int g_argm[NROWS_MAX];
__device__ __align__(16) int g_first[1024];
__device__ __align__(16) int g_idx[1024];

// ---------------------------------------------------------------------------
// K0: reset first-occurrence table (graph replays re-run this each time)
// ---------------------------------------------------------------------------
__global__ void k_init() {
    g_first[threadIdx.x] = 0x7FFFFFFF;
}

// ---------------------------------------------------------------------------
// K1: per-row argmax (original index space) + first-occurrence via atomicMin.
// One warp per row; 250 float4 per row split across 32 lanes (MLP=8).
// ---------------------------------------------------------------------------
__global__ void k_argmax(const float* __restrict__ in,
                         const int* __restrict__ labels, int N) {
    int w    = (blockIdx.x * blockDim.x + threadIdx.x) >> 5;
    int lane = threadIdx.x & 31;
    if (w >= N) return;

    const float4* rp = reinterpret_cast<const float4*>(in) + (size_t)w * 250;
    float bv = -3.402823466e38f;
    int   bi = 0;
#pragma unroll
    for (int it = 0; it < 7; ++it) {           // k = lane + 32*it <= 223 < 250
        int k = lane + it * 32;
        float4 v = rp[k];
        int b = k * 4;
        if (v.x > bv) { bv = v.x; bi = b;     }
        if (v.y > bv) { bv = v.y; bi = b + 1; }
        if (v.z > bv) { bv = v.z; bi = b + 2; }
        if (v.w > bv) { bv = v.w; bi = b + 3; }
    }
    if (lane < 26) {                            // tail: k = lane + 224 < 250
        int k = lane + 224;
        float4 v = rp[k];
        int b = k * 4;
        if (v.x > bv) { bv = v.x; bi = b;     }
        if (v.y > bv) { bv = v.y; bi = b + 1; }
        if (v.z > bv) { bv = v.z; bi = b + 2; }
        if (v.w > bv) { bv = v.w; bi = b + 3; }
    }
#pragma unroll
    for (int off = 16; off > 0; off >>= 1) {
        float ov = __shfl_down_sync(0xFFFFFFFFu, bv, off);
        int   oi = __shfl_down_sync(0xFFFFFFFFu, bi, off);
        if (ov > bv || (ov == bv && oi < bi)) { bv = ov; bi = oi; }
    }
    if (lane == 0) {
        g_argm[w] = bi;
        atomicMin(&g_first[labels[w]], w);
    }
}

// ---------------------------------------------------------------------------
// K2: single block.
//   Phase A: rank events (first occurrences) by row via 32768-bit bitmap +
//            1024-word popc prefix-sum (replaces O(L^2) rank loop).
//   Phase B: serial scan with 1-ahead prefetch + alias patching:
//            all smem loads of an iteration are independent (single LDS level),
//            the prefetched pinv[m_{e+1}] is patched in registers against this
//            event's two stores. Swap is branchless (r==lab => no-op rewrite).
//   Phase C: invert pinv -> g_idx.
//
// Event semantics: r = pinv[m]; if (r != lab) swap(pinv[r], pinv[lab]).
// ---------------------------------------------------------------------------
__global__ void k_scan() {
    __shared__ unsigned  sbit[1024];   // 32768-bit row bitmap
    __shared__ int       sexc[1024];   // exclusive popc prefix per word
    __shared__ long long ev[1024];     // packed (m << 32) | lab, sorted by row
    __shared__ int       pinv[1024];
    __shared__ int       wsum[32];
    __shared__ int       sE;

    int t = threadIdx.x;
    int lane = t & 31, w = t >> 5;

    sbit[t] = 0u;
    pinv[t] = t;
    int myf = (t < LBL) ? g_first[t] : 0x7FFFFFFF;
    __syncthreads();

    if (myf != 0x7FFFFFFF)
        atomicOr(&sbit[myf >> 5], 1u << (myf & 31));
    __syncthreads();

    // block prefix-sum of per-word popcounts
    unsigned word = sbit[t];
    int c = __popc(word);
    int x = c;
#pragma unroll
    for (int o = 1; o < 32; o <<= 1) {
        int y = __shfl_up_sync(0xFFFFFFFFu, x, o);
        if (lane >= o) x += y;
    }
    if (lane == 31) wsum[w] = x;
    __syncthreads();
    if (t < 32) {
        int v = wsum[t];
        int iv = v;
#pragma unroll
        for (int o = 1; o < 32; o <<= 1) {
            int y = __shfl_up_sync(0xFFFFFFFFu, iv, o);
            if (t >= o) iv += y;
        }
        wsum[t] = iv - v;          // exclusive warp offset
        if (t == 31) sE = iv;      // total number of events
    }
    __syncthreads();
    sexc[t] = wsum[w] + (x - c);
    __syncthreads();

    if (myf != 0x7FFFFFFF) {
        unsigned wv = sbit[myf >> 5];
        int rank = sexc[myf >> 5] + __popc(wv & ((1u << (myf & 31)) - 1u));
        ev[rank] = ((long long)g_argm[myf] << 32) | (unsigned)t;
    }
    __syncthreads();

    // Phase B: serial event loop (thread 0)
    if (t == 0) {
        int E = sE;
        if (E > 0) {
            long long e0 = ev[0];
            int m   = (int)(e0 >> 32);
            int lab = (int)(e0 & 0xFFFFFFFF);
            int r   = pinv[m];
            for (int e = 0; e < E; ++e) {
                // independent loads, all issued at iteration start
                int pl = pinv[lab];          // ordered after prev iter's stores
                int pr = pinv[r];
                int m1 = 0, lab1 = 0, nm = 0;
                if (e + 1 < E) {
                    long long e1 = ev[e + 1];
                    m1   = (int)(e1 >> 32);
                    lab1 = (int)(e1 & 0xFFFFFFFF);
                    nm   = pinv[m1];         // issued BEFORE this event's stores
                }
                // branchless swap (r==lab => same-value rewrite, no-op)
                pinv[r]   = pl;
                pinv[lab] = pr;
                // patch the prefetched value against this event's stores
                int rn = nm;
                if (m1 == r)   rn = pl;
                if (m1 == lab) rn = pr;
                m = m1; lab = lab1; r = rn;
            }
        }
    }
    __syncthreads();

    // Phase C: forward permutation idx[pinv[v]] = v (bijection -> full cover)
    if (t < LBL) g_idx[pinv[t]] = t;
}

// ---------------------------------------------------------------------------
// K3: out[n,j] = in[n, idx[j]]. One warp per row; each warp stages its 4 KB
// row in a private smem slab (8x LDG.128 per lane, MLP=8), __syncwarp, smem
// gather, coalesced float4 write. Single block-wide sync (idx staging) only.
// ---------------------------------------------------------------------------
__global__ void k_gather(const float* __restrict__ in,
                         float* __restrict__ out, int N) {
    __shared__ int4  sidx[250];
    __shared__ float srow[8][1000];

    int t    = threadIdx.x;
    int wid  = t >> 5;
    int lane = t & 31;

    if (t < 250) sidx[t] = reinterpret_cast<const int4*>(g_idx)[t];

    int row = blockIdx.x * 8 + wid;
    float4 v[8];
    if (row < N) {
        const float4* rp = reinterpret_cast<const float4*>(in + (size_t)row * 1000);
#pragma unroll
        for (int it = 0; it < 8; ++it) {
            int k = lane + it * 32;
            if (k < 250) v[it] = rp[k];
        }
    }
    __syncthreads();   // covers sidx (row loads already in flight)

    if (row < N) {
        float* my = &srow[wid][0];
#pragma unroll
        for (int it = 0; it < 8; ++it) {
            int k = lane + it * 32;
            if (k < 250) reinterpret_cast<float4*>(my)[k] = v[it];
        }
        __syncwarp();
        float4* op = reinterpret_cast<float4*>(out + (size_t)row * 1000);
#pragma unroll
        for (int it = 0; it < 8; ++it) {
            int k = lane + it * 32;
            if (k < 250) {
                int4 ii = sidx[k];
                float4 o;
                o.x = my[ii.x];
                o.y = my[ii.y];
                o.z = my[ii.z];
                o.w = my[ii.w];
                op[k] = o;
            }
        }
    }
}

// ---------------------------------------------------------------------------
extern "C" void kernel_launch(void* const* d_in, const int* in_sizes, int n_in,
                              void* d_out, int out_size) {
    const float* in     = (const float*)d_in[0];
    const int*   labels = (const int*)d_in[1];
    float*       out    = (float*)d_out;
    int N = in_sizes[1];   // 32768 rows; L = 1000

    k_init  <<<1, 1024>>>();
    k_argmax<<<(N + 7) / 8, 256>>>(in, labels, N);
    k_scan  <<<1, 1024>>>();
    k_gather<<<(N + 7) / 8, 256>>>(in, out, N);
}

// round 3
// speedup vs baseline: 1.5542x; 1.0611x over previous
#include <cuda_runtime.h>
#include <cuda_bf16.h>

// Problem constants: outputs [64,512,1000] f32, labels [64,512] i32
#define LBL 1000
#define NROWS_MAX 32768

__device__ int g_argm[NROWS_MAX];
__device__ __align__(16) int g_first[1024];   // static zero-init; k_scan re-zeros
__device__ __align__(16) int g_idx[1024];     // holds pinv (inverse permutation)

// ---------------------------------------------------------------------------
// K1: per-row argmax (original index space) + first-occurrence.
// First-occurrence encoded as max(N - w) over rows w with label lab, so the
// "empty" state is 0 => no init kernel needed (static zero + scan self-reset).
// One warp per row; 250 float4 per row across 32 lanes (MLP=8).
// ---------------------------------------------------------------------------
__global__ __launch_bounds__(256) void k_argmax(const float* __restrict__ in,
                                                const int* __restrict__ labels,
                                                int N) {
    int w    = (blockIdx.x * blockDim.x + threadIdx.x) >> 5;
    int lane = threadIdx.x & 31;
    if (w >= N) return;

    const float4* rp = reinterpret_cast<const float4*>(in) + (size_t)w * 250;
    float bv = -3.402823466e38f;
    int   bi = 0;
#pragma unroll
    for (int it = 0; it < 7; ++it) {           // k = lane + 32*it <= 223 < 250
        int k = lane + it * 32;
        float4 v = rp[k];
        int b = k * 4;
        if (v.x > bv) { bv = v.x; bi = b;     }
        if (v.y > bv) { bv = v.y; bi = b + 1; }
        if (v.z > bv) { bv = v.z; bi = b + 2; }
        if (v.w > bv) { bv = v.w; bi = b + 3; }
    }
    if (lane < 26) {                            // tail: k = lane + 224 < 250
        int k = lane + 224;
        float4 v = rp[k];
        int b = k * 4;
        if (v.x > bv) { bv = v.x; bi = b;     }
        if (v.y > bv) { bv = v.y; bi = b + 1; }
        if (v.z > bv) { bv = v.z; bi = b + 2; }
        if (v.w > bv) { bv = v.w; bi = b + 3; }
    }
#pragma unroll
    for (int off = 16; off > 0; off >>= 1) {
        float ov = __shfl_down_sync(0xFFFFFFFFu, bv, off);
        int   oi = __shfl_down_sync(0xFFFFFFFFu, bi, off);
        if (ov > bv || (ov == bv && oi < bi)) { bv = ov; bi = oi; }
    }
    if (lane == 0) {
        g_argm[w] = bi;
        atomicMax(&g_first[labels[w]], N - w);   // first occurrence = max(N-w)
    }
}

// ---------------------------------------------------------------------------
// K2: single block.
//   Phase A: rank events (first occurrences) by row via 32768-bit bitmap +
//            1024-word popc prefix-sum. Self-resets g_first for next replay.
//   Phase B: serial scan (thread 0) with 1-ahead prefetch of BOTH
//            pinv[m_{e+1}] and pinv[lab_{e+1}], register-patched against the
//            current event's stores. Chain: patch -> LDS pinv[r] -> stores.
//   Output: g_idx = pinv directly (gather scatters with pinv; no inversion).
//
// Event semantics: r = pinv[m]; if (r != lab) swap(pinv[r], pinv[lab]).
// ---------------------------------------------------------------------------
__global__ __launch_bounds__(1024) void k_scan(int N) {
    __shared__ unsigned  sbit[1024];   // 32768-bit row bitmap
    __shared__ int       sexc[1024];   // exclusive popc prefix per word
    __shared__ long long ev[1024];     // packed (m << 32) | lab, sorted by row
    __shared__ int       pinv[1024];
    __shared__ int       wsum[32];
    __shared__ int       sE;

    int t = threadIdx.x;
    int lane = t & 31, w = t >> 5;

    sbit[t] = 0u;
    pinv[t] = t;
    int enc = (t < LBL) ? g_first[t] : 0;
    g_first[t] = 0;                    // reset for next graph replay
    int myf = (enc > 0) ? (N - enc) : -1;
    __syncthreads();

    if (myf >= 0)
        atomicOr(&sbit[myf >> 5], 1u << (myf & 31));
    __syncthreads();

    // block prefix-sum of per-word popcounts
    unsigned word = sbit[t];
    int c = __popc(word);
    int x = c;
#pragma unroll
    for (int o = 1; o < 32; o <<= 1) {
        int y = __shfl_up_sync(0xFFFFFFFFu, x, o);
        if (lane >= o) x += y;
    }
    if (lane == 31) wsum[w] = x;
    __syncthreads();
    if (t < 32) {
        int v = wsum[t];
        int iv = v;
#pragma unroll
        for (int o = 1; o < 32; o <<= 1) {
            int y = __shfl_up_sync(0xFFFFFFFFu, iv, o);
            if (t >= o) iv += y;
        }
        wsum[t] = iv - v;          // exclusive warp offset
        if (t == 31) sE = iv;      // total number of events
    }
    __syncthreads();
    sexc[t] = wsum[w] + (x - c);
    __syncthreads();

    if (myf >= 0) {
        unsigned wv = sbit[myf >> 5];
        int rank = sexc[myf >> 5] + __popc(wv & ((1u << (myf & 31)) - 1u));
        ev[rank] = ((long long)g_argm[myf] << 32) | (unsigned)t;
    }
    __syncthreads();

    // Phase B: serial event loop (thread 0)
    if (t == 0) {
        int E = sE;
        if (E > 0) {
            long long e0 = ev[0];
            int m   = (int)(e0 >> 32);
            int lab = (int)(e0 & 0xFFFFFFFF);
            int r   = pinv[m];
            int pl  = pinv[lab];
            for (int e = 0; e < E; ++e) {
                int pr = pinv[r];
                int m1 = 0, lab1 = 0, nm = 0, nl = 0;
                if (e + 1 < E) {
                    long long e1 = ev[e + 1];
                    m1   = (int)(e1 >> 32);
                    lab1 = (int)(e1 & 0xFFFFFFFF);
                    nm   = pinv[m1];         // issued BEFORE this event's stores
                    nl   = pinv[lab1];
                }
                // branchless swap (r==lab => same-value rewrite, no-op)
                pinv[r]   = pl;
                pinv[lab] = pr;
                // patch both prefetches against this event's two stores
                int rn = nm;
                if (m1 == r)     rn = pl;
                if (m1 == lab)   rn = pr;
                int pln = nl;
                if (lab1 == r)   pln = pl;
                if (lab1 == lab) pln = pr;
                m = m1; lab = lab1; r = rn; pl = pln;
            }
        }
    }
    __syncthreads();

    if (t < LBL) g_idx[t] = pinv[t];   // store pinv directly (scatter gather)
}

// ---------------------------------------------------------------------------
// K3: out[n, pinv[k]] = in[n, k]  (equivalent to out[n,j] = in[n, idx[j]]).
// One warp per row, rows processed in REVERSE order so the first-scheduled
// blocks touch the lines k_argmax cached most recently in L2.
// Stage permuted via scalar STS (issue-only, no load-result latency), then
// coalesced float4 LDS -> streaming float4 STG (__stcs keeps input in L2).
// ---------------------------------------------------------------------------
__global__ __launch_bounds__(256) void k_gather(const float* __restrict__ in,
                                                float* __restrict__ out, int N) {
    __shared__ int4  sidx[250];        // pinv, packed
    __shared__ float srow[8][1000];

    int t    = threadIdx.x;
    int wid  = t >> 5;
    int lane = t & 31;

    if (t < 250) sidx[t] = reinterpret_cast<const int4*>(g_idx)[t];

    int row = N - 1 - (blockIdx.x * 8 + wid);   // reverse order for L2 reuse
    float4 v[8];
    if (row >= 0) {
        const float4* rp = reinterpret_cast<const float4*>(in + (size_t)row * 1000);
#pragma unroll
        for (int it = 0; it < 8; ++it) {
            int k = lane + it * 32;
            if (k < 250) v[it] = rp[k];
        }
    }
    __syncthreads();   // covers sidx (row loads already in flight)

    if (row >= 0) {
        float* my = &srow[wid][0];
#pragma unroll
        for (int it = 0; it < 8; ++it) {
            int k = lane + it * 32;
            if (k < 250) {
                int4 p = sidx[k];
                my[p.x] = v[it].x;     // permuted scatter into smem
                my[p.y] = v[it].y;
                my[p.z] = v[it].z;
                my[p.w] = v[it].w;
            }
        }
        __syncwarp();
        float4* op = reinterpret_cast<float4*>(out + (size_t)row * 1000);
        const float4* mv = reinterpret_cast<const float4*>(my);
#pragma unroll
        for (int it = 0; it < 8; ++it) {
            int k = lane + it * 32;
            if (k < 250) __stcs(&op[k], mv[k]);   // coalesced streaming write
        }
    }
}

// ---------------------------------------------------------------------------
extern "C" void kernel_launch(void* const* d_in, const int* in_sizes, int n_in,
                              void* d_out, int out_size) {
    const float* in     = (const float*)d_in[0];
    const int*   labels = (const int*)d_in[1];
    float*       out    = (float*)d_out;
    int N = in_sizes[1];   // 32768 rows; L = 1000

    k_argmax<<<(N + 7) / 8, 256>>>(in, labels, N);
    k_scan  <<<1, 1024>>>(N);
    k_gather<<<(N + 7) / 8, 256>>>(in, out, N);
}